// round 8
// baseline (speedup 1.0000x reference)
#include <cuda_runtime.h>

#define N_NODES 50000
#define N_EDGES 800000
#define C 64
#define CE 32
#define MAXDEG 64   // P(Binomial(800k,1/50k) > 64) ~ 1e-21 per node; clamped

// ---- device scratch (no allocation allowed) ----
__device__ float g_xw[N_NODES * C];                 // x @ weight_node
__device__ float g_sdst[N_NODES];                   // <xw[n], wa[0:64]>
__device__ float g_ssrc[N_NODES];                   // <xw[n], wa[96:160]>
__device__ int   g_cnt[N_NODES];                    // per-dst edge counter
__device__ unsigned long long g_pack[N_NODES * MAXDEG]; // (ev,src) bins per dst
__device__ int   g_is64;                            // edge_index is int64?

#define FMA_F32X2(d, a, b) \
    asm("fma.rn.f32x2 %0, %1, %2, %0;" : "+l"(d) : "l"(a), "l"(b))
#define PACK_F32X2(d, lo, hi) \
    asm("mov.b64 %0, {%1, %2};" : "=l"(d) : "f"(lo), "f"(hi))

// ---------------------------------------------------------------------------
// K-1: detect edge_index dtype (int64 vs silently-int32 from JAX).
__global__ void k_detect(const int* __restrict__ ei32) {
    __shared__ int any_nonzero;
    if (threadIdx.x == 0) any_nonzero = 0;
    __syncthreads();
    int v = ei32[2 * threadIdx.x + 1];   // odd words: int64 hi-halves == 0
    if (v != 0) atomicOr(&any_nonzero, 1);
    __syncthreads();
    if (threadIdx.x == 0) g_is64 = any_nonzero ? 0 : 1;
}

// K0: zero per-node counters
__global__ void k_zero() {
    int idx = blockIdx.x * blockDim.x + threadIdx.x;
    if (idx < N_NODES) g_cnt[idx] = 0;
}

// ---------------------------------------------------------------------------
// K1: xw = x @ W  (128 rows x 64 cols per 256-thread block), fused per-node
// attention scores in the epilogue. Packed fma.rn.f32x2 mainloop.
__global__ void __launch_bounds__(256, 4)
k_gemm(const float* __restrict__ x, const float* __restrict__ W,
       const float* __restrict__ wa) {
    __shared__ float ws[64][64];        // W[k][c]
    __shared__ float xs_t[64][132];     // x transposed: [k][row], 16B-aligned rows
    const int tid = threadIdx.x;
    const int row0 = blockIdx.x * 128;

    for (int i = tid; i < 64 * 16; i += 256)
        ((float4*)&ws[0][0])[i] = ((const float4*)W)[i];
    for (int i = tid; i < 128 * 16; i += 256) {
        int r = i >> 4, c4 = i & 15;
        int gr = row0 + r;
        float4 v = (gr < N_NODES) ? ((const float4*)(x + (size_t)gr * 64))[c4]
                                  : make_float4(0.f, 0.f, 0.f, 0.f);
        xs_t[c4 * 4 + 0][r] = v.x;
        xs_t[c4 * 4 + 1][r] = v.y;
        xs_t[c4 * 4 + 2][r] = v.z;
        xs_t[c4 * 4 + 3][r] = v.w;
    }
    __syncthreads();

    const int cg = tid & 7;    // cols cg*8 .. cg*8+7
    const int rg = tid >> 3;   // rows rg*4 .. rg*4+3

    unsigned long long acc[4][4];
    #pragma unroll
    for (int r = 0; r < 4; r++)
        #pragma unroll
        for (int p = 0; p < 4; p++) acc[r][p] = 0ull;

    #pragma unroll 8
    for (int k = 0; k < 64; k++) {
        float4 xv = *(const float4*)&xs_t[k][rg * 4];
        ulonglong2 wA = *(const ulonglong2*)&ws[k][cg * 8];
        ulonglong2 wB = *(const ulonglong2*)&ws[k][cg * 8 + 4];
        unsigned long long xx[4];
        PACK_F32X2(xx[0], xv.x, xv.x);
        PACK_F32X2(xx[1], xv.y, xv.y);
        PACK_F32X2(xx[2], xv.z, xv.z);
        PACK_F32X2(xx[3], xv.w, xv.w);
        #pragma unroll
        for (int r = 0; r < 4; r++) {
            FMA_F32X2(acc[r][0], xx[r], wA.x);
            FMA_F32X2(acc[r][1], xx[r], wA.y);
            FMA_F32X2(acc[r][2], xx[r], wB.x);
            FMA_F32X2(acc[r][3], xx[r], wB.y);
        }
    }

    float wad[8], was[8];
    #pragma unroll
    for (int j = 0; j < 8; j++) {
        wad[j] = wa[cg * 8 + j];
        was[j] = wa[96 + cg * 8 + j];
    }

    #pragma unroll
    for (int r = 0; r < 4; r++) {
        int row = row0 + rg * 4 + r;
        float sd = 0.f, ss = 0.f;
        float v[8];
        #pragma unroll
        for (int p = 0; p < 4; p++) {
            v[2 * p]     = __uint_as_float((unsigned)(acc[r][p] & 0xffffffffull));
            v[2 * p + 1] = __uint_as_float((unsigned)(acc[r][p] >> 32));
        }
        #pragma unroll
        for (int j = 0; j < 8; j++) {
            sd += v[j] * wad[j];
            ss += v[j] * was[j];
        }
        #pragma unroll
        for (int o = 4; o; o >>= 1) {
            sd += __shfl_xor_sync(0xffffffffu, sd, o);
            ss += __shfl_xor_sync(0xffffffffu, ss, o);
        }
        if (row < N_NODES) {
            ulonglong2* dst = (ulonglong2*)(g_xw + (size_t)row * 64 + cg * 8);
            dst[0] = make_ulonglong2(acc[r][0], acc[r][1]);
            dst[1] = make_ulonglong2(acc[r][2], acc[r][3]);
            if (cg == 0) { g_sdst[row] = sd; g_ssrc[row] = ss; }
        }
    }
}

// ---------------------------------------------------------------------------
// K2 (pass C): per edge, compute ev = exp(leakyrelu(alpha)) and BIN it by dst:
//   pos = atomicAdd(&cnt[dst],1);  g_pack[dst*64+pos] = (ev_bits<<32)|src
// 4 edges per warp, 8 lanes per edge; only lane q==0 does the atomic+store.
__global__ void k_edgeC(const int* __restrict__ ei32,
                        const float* __restrict__ ea,
                        const float* __restrict__ wa) {
    int warp = (blockIdx.x * blockDim.x + threadIdx.x) >> 5;
    int lane = threadIdx.x & 31;
    int g = lane >> 3, q = lane & 7;
    int e = warp * 4 + g;
    if (e >= N_EDGES) return;

    // 32-dim edge_attr dot: 8 lanes x float4
    float4 v = __ldg(((const float4*)(ea + (size_t)e * CE)) + q);
    float4 w = __ldg(((const float4*)(wa + 64)) + q);
    float p = v.x * w.x + v.y * w.y + v.z * w.z + v.w * w.w;
    p += __shfl_xor_sync(0xffffffffu, p, 4);
    p += __shfl_xor_sync(0xffffffffu, p, 2);
    p += __shfl_xor_sync(0xffffffffu, p, 1);

    if (q == 0) {
        int src, dst;
        if (g_is64) {
            src = __ldg(ei32 + 2 * e);
            dst = __ldg(ei32 + 2 * N_EDGES + 2 * e);
        } else {
            src = __ldg(ei32 + e);
            dst = __ldg(ei32 + N_EDGES + e);
        }
        float alpha = p + __ldg(g_sdst + dst) + __ldg(g_ssrc + src);
        alpha = alpha > 0.f ? alpha : 0.2f * alpha;   // leaky_relu
        float ev = __expf(alpha);                      // max-shift safe to omit
        int pos = atomicAdd(&g_cnt[dst], 1) & (MAXDEG - 1);
        g_pack[(size_t)dst * MAXDEG + pos] =
            ((unsigned long long)__float_as_uint(ev) << 32) | (unsigned)src;
    }
}

// ---------------------------------------------------------------------------
// K3 (pass D): one warp per node. Two 16-lane groups each process one binned
// edge per iteration: gather xw[src] (float4/lane), accumulate ev*xw and
// sum(ev) in registers. Final xor-16 reduce, then ONE normalized+bias store.
// No output atomics at all.
__global__ void k_accum(const float* __restrict__ bias, float* __restrict__ out) {
    int n = blockIdx.x * (blockDim.x >> 5) + (threadIdx.x >> 5);
    if (n >= N_NODES) return;
    int lane = threadIdx.x & 31;
    int g = lane >> 4, q = lane & 15;

    int cnt = g_cnt[n];
    if (cnt > MAXDEG) cnt = MAXDEG;
    const unsigned long long* packs = g_pack + (size_t)n * MAXDEG;

    float4 acc = make_float4(0.f, 0.f, 0.f, 0.f);
    float s = 0.f;
    for (int j = 0; j < cnt; j += 2) {
        int idx = j + g;
        if (idx < cnt) {
            unsigned long long pk = __ldg(packs + idx);
            int src  = (int)(unsigned)(pk & 0xffffffffull);
            float ev = __uint_as_float((unsigned)(pk >> 32));
            float4 xv = __ldg(((const float4*)(g_xw + (size_t)src * 64)) + q);
            acc.x += ev * xv.x;
            acc.y += ev * xv.y;
            acc.z += ev * xv.z;
            acc.w += ev * xv.w;
            s += ev;
        }
    }
    // combine the two 16-lane groups
    acc.x += __shfl_xor_sync(0xffffffffu, acc.x, 16);
    acc.y += __shfl_xor_sync(0xffffffffu, acc.y, 16);
    acc.z += __shfl_xor_sync(0xffffffffu, acc.z, 16);
    acc.w += __shfl_xor_sync(0xffffffffu, acc.w, 16);
    s     += __shfl_xor_sync(0xffffffffu, s,     16);

    if (lane < 16) {
        float inv = 1.0f / (s + 1e-16f);
        float4 b = __ldg(((const float4*)bias) + q);
        float4 o = make_float4(acc.x * inv + b.x, acc.y * inv + b.y,
                               acc.z * inv + b.z, acc.w * inv + b.w);
        ((float4*)(out + (size_t)n * 64))[q] = o;
    }
}

// ---------------------------------------------------------------------------
extern "C" void kernel_launch(void* const* d_in, const int* in_sizes, int n_in,
                              void* d_out, int out_size) {
    const float* x    = nullptr;
    const int*   ei32 = nullptr;
    const float* ea   = nullptr;
    const float* W    = nullptr;
    const float* wa   = nullptr;
    const float* bias = nullptr;
    for (int i = 0; i < n_in; i++) {
        switch (in_sizes[i]) {
            case N_NODES * C:      x    = (const float*)d_in[i]; break;
            case 2 * N_EDGES:      ei32 = (const int*)d_in[i];   break;
            case N_EDGES * CE:     ea   = (const float*)d_in[i]; break;
            case C * C:            W    = (const float*)d_in[i]; break;
            case 2 * C + CE:       wa   = (const float*)d_in[i]; break;
            case C:                bias = (const float*)d_in[i]; break;
        }
    }
    float* out = (float*)d_out;

    k_detect<<<1, 256>>>(ei32);
    k_zero<<<(N_NODES + 255) / 256, 256>>>();
    k_gemm<<<(N_NODES + 127) / 128, 256>>>(x, W, wa);
    k_edgeC<<<(N_EDGES / 4 + 7) / 8, 256>>>(ei32, ea, wa);
    k_accum<<<(N_NODES + 7) / 8, 256>>>(bias, out);
}

// round 9
// speedup vs baseline: 1.1478x; 1.1478x over previous
#include <cuda_runtime.h>

#define N_NODES 50000
#define N_EDGES 800000
#define C 64
#define CE 32
#define MAXDEG 64   // P(Binomial(800k,1/50k) > 64) ~ 1e-21 per node; clamped

// ---- device scratch (no allocation allowed) ----
__device__ float g_xw[N_NODES * C];                 // x @ weight_node
__device__ float g_sdst[N_NODES];                   // <xw[n], wa[0:64]>
__device__ float g_ssrc[N_NODES];                   // <xw[n], wa[96:160]>
__device__ int   g_cnt[N_NODES];                    // per-dst edge counter
__device__ unsigned long long g_pack[N_NODES * MAXDEG]; // (ev,src) bins per dst
__device__ int   g_is64;                            // edge_index is int64?

#define FMA_F32X2(d, a, b) \
    asm("fma.rn.f32x2 %0, %1, %2, %0;" : "+l"(d) : "l"(a), "l"(b))
#define PACK_F32X2(d, lo, hi) \
    asm("mov.b64 %0, {%1, %2};" : "=l"(d) : "f"(lo), "f"(hi))

// ---------------------------------------------------------------------------
// K-1: detect edge_index dtype (int64 vs silently-int32 from JAX).
__global__ void k_detect(const int* __restrict__ ei32) {
    __shared__ int any_nonzero;
    if (threadIdx.x == 0) any_nonzero = 0;
    __syncthreads();
    int v = ei32[2 * threadIdx.x + 1];   // odd words: int64 hi-halves == 0
    if (v != 0) atomicOr(&any_nonzero, 1);
    __syncthreads();
    if (threadIdx.x == 0) g_is64 = any_nonzero ? 0 : 1;
}

// K0: zero per-node counters
__global__ void k_zero() {
    int idx = blockIdx.x * blockDim.x + threadIdx.x;
    if (idx < N_NODES) g_cnt[idx] = 0;
}

// ---------------------------------------------------------------------------
// K1: xw = x @ W  (128 rows x 64 cols per 256-thread block), fused per-node
// attention scores in the epilogue. Packed fma.rn.f32x2 mainloop.
__global__ void __launch_bounds__(256, 4)
k_gemm(const float* __restrict__ x, const float* __restrict__ W,
       const float* __restrict__ wa) {
    __shared__ float ws[64][64];        // W[k][c]
    __shared__ float xs_t[64][132];     // x transposed: [k][row], 16B-aligned rows
    const int tid = threadIdx.x;
    const int row0 = blockIdx.x * 128;

    for (int i = tid; i < 64 * 16; i += 256)
        ((float4*)&ws[0][0])[i] = ((const float4*)W)[i];
    for (int i = tid; i < 128 * 16; i += 256) {
        int r = i >> 4, c4 = i & 15;
        int gr = row0 + r;
        float4 v = (gr < N_NODES) ? ((const float4*)(x + (size_t)gr * 64))[c4]
                                  : make_float4(0.f, 0.f, 0.f, 0.f);
        xs_t[c4 * 4 + 0][r] = v.x;
        xs_t[c4 * 4 + 1][r] = v.y;
        xs_t[c4 * 4 + 2][r] = v.z;
        xs_t[c4 * 4 + 3][r] = v.w;
    }
    __syncthreads();

    const int cg = tid & 7;    // cols cg*8 .. cg*8+7
    const int rg = tid >> 3;   // rows rg*4 .. rg*4+3

    unsigned long long acc[4][4];
    #pragma unroll
    for (int r = 0; r < 4; r++)
        #pragma unroll
        for (int p = 0; p < 4; p++) acc[r][p] = 0ull;

    #pragma unroll 8
    for (int k = 0; k < 64; k++) {
        float4 xv = *(const float4*)&xs_t[k][rg * 4];
        ulonglong2 wA = *(const ulonglong2*)&ws[k][cg * 8];
        ulonglong2 wB = *(const ulonglong2*)&ws[k][cg * 8 + 4];
        unsigned long long xx[4];
        PACK_F32X2(xx[0], xv.x, xv.x);
        PACK_F32X2(xx[1], xv.y, xv.y);
        PACK_F32X2(xx[2], xv.z, xv.z);
        PACK_F32X2(xx[3], xv.w, xv.w);
        #pragma unroll
        for (int r = 0; r < 4; r++) {
            FMA_F32X2(acc[r][0], xx[r], wA.x);
            FMA_F32X2(acc[r][1], xx[r], wA.y);
            FMA_F32X2(acc[r][2], xx[r], wB.x);
            FMA_F32X2(acc[r][3], xx[r], wB.y);
        }
    }

    float wad[8], was[8];
    #pragma unroll
    for (int j = 0; j < 8; j++) {
        wad[j] = wa[cg * 8 + j];
        was[j] = wa[96 + cg * 8 + j];
    }

    #pragma unroll
    for (int r = 0; r < 4; r++) {
        int row = row0 + rg * 4 + r;
        float sd = 0.f, ss = 0.f;
        float v[8];
        #pragma unroll
        for (int p = 0; p < 4; p++) {
            v[2 * p]     = __uint_as_float((unsigned)(acc[r][p] & 0xffffffffull));
            v[2 * p + 1] = __uint_as_float((unsigned)(acc[r][p] >> 32));
        }
        #pragma unroll
        for (int j = 0; j < 8; j++) {
            sd += v[j] * wad[j];
            ss += v[j] * was[j];
        }
        #pragma unroll
        for (int o = 4; o; o >>= 1) {
            sd += __shfl_xor_sync(0xffffffffu, sd, o);
            ss += __shfl_xor_sync(0xffffffffu, ss, o);
        }
        if (row < N_NODES) {
            ulonglong2* dst = (ulonglong2*)(g_xw + (size_t)row * 64 + cg * 8);
            dst[0] = make_ulonglong2(acc[r][0], acc[r][1]);
            dst[1] = make_ulonglong2(acc[r][2], acc[r][3]);
            if (cg == 0) { g_sdst[row] = sd; g_ssrc[row] = ss; }
        }
    }
}

// ---------------------------------------------------------------------------
// K2 (pass C): 16 edges per warp, 8 lanes per edge, 4 edges per 8-lane group
// with all 4 edge_attr float4 loads issued up front (MLP=4 on DRAM stream).
//   ev = exp(leakyrelu(<ea,wa>+sdst[dst]+ssrc[src]));  bin (ev,src) by dst.
__global__ void k_edgeC(const int* __restrict__ ei32,
                        const float* __restrict__ ea,
                        const float* __restrict__ wa) {
    int warp = (blockIdx.x * blockDim.x + threadIdx.x) >> 5;
    int lane = threadIdx.x & 31;
    int g = lane >> 3, q = lane & 7;
    int e0 = warp * 16 + g;              // edges e0 + 4*i, i=0..3
    if (e0 >= N_EDGES) return;

    // 4 independent 16B loads -> MLP=4
    float4 v[4];
    #pragma unroll
    for (int i = 0; i < 4; i++)
        v[i] = __ldg(((const float4*)ea) + (size_t)(e0 + 4 * i) * 8 + q);
    float4 w = __ldg(((const float4*)(wa + 64)) + q);

    float p[4];
    #pragma unroll
    for (int i = 0; i < 4; i++)
        p[i] = v[i].x * w.x + v[i].y * w.y + v[i].z * w.z + v[i].w * w.w;
    // 4 independent butterfly chains (latency overlaps via ILP)
    #pragma unroll
    for (int o = 4; o; o >>= 1)
        #pragma unroll
        for (int i = 0; i < 4; i++)
            p[i] += __shfl_xor_sync(0xffffffffu, p[i], o);

    if (q == 0) {
        int is64 = g_is64;
        #pragma unroll
        for (int i = 0; i < 4; i++) {
            int e = e0 + 4 * i;
            int src, dst;
            if (is64) {
                src = __ldg(ei32 + 2 * e);
                dst = __ldg(ei32 + 2 * N_EDGES + 2 * e);
            } else {
                src = __ldg(ei32 + e);
                dst = __ldg(ei32 + N_EDGES + e);
            }
            float alpha = p[i] + __ldg(g_sdst + dst) + __ldg(g_ssrc + src);
            alpha = alpha > 0.f ? alpha : 0.2f * alpha;   // leaky_relu
            float ev = __expf(alpha);                      // max-shift safe to omit
            int pos = atomicAdd(&g_cnt[dst], 1) & (MAXDEG - 1);
            g_pack[(size_t)dst * MAXDEG + pos] =
                ((unsigned long long)__float_as_uint(ev) << 32) | (unsigned)src;
        }
    }
}

// ---------------------------------------------------------------------------
// K3 (pass D): one warp per node; two 16-lane groups. Unrolled x4: batch-load
// 4 packed entries, then 4 independent xw-row gathers (MLP=4), accumulate in
// registers. Final xor-16 reduce + ONE normalized store. No output atomics.
__global__ void k_accum(const float* __restrict__ bias, float* __restrict__ out) {
    int n = blockIdx.x * (blockDim.x >> 5) + (threadIdx.x >> 5);
    if (n >= N_NODES) return;
    int lane = threadIdx.x & 31;
    int g = lane >> 4, q = lane & 15;

    int cnt = g_cnt[n];
    if (cnt > MAXDEG) cnt = MAXDEG;
    const unsigned long long* packs = g_pack + (size_t)n * MAXDEG;

    float4 acc = make_float4(0.f, 0.f, 0.f, 0.f);
    float s = 0.f;
    int j = 0;
    for (; j + 8 <= cnt; j += 8) {
        unsigned long long pk[4];
        #pragma unroll
        for (int i = 0; i < 4; i++)
            pk[i] = __ldg(packs + j + 2 * i + g);
        float4 xv[4];
        float ev[4];
        #pragma unroll
        for (int i = 0; i < 4; i++) {
            int src = (int)(unsigned)(pk[i] & 0xffffffffull);
            ev[i] = __uint_as_float((unsigned)(pk[i] >> 32));
            xv[i] = __ldg(((const float4*)(g_xw + (size_t)src * 64)) + q);
        }
        #pragma unroll
        for (int i = 0; i < 4; i++) {
            acc.x += ev[i] * xv[i].x;
            acc.y += ev[i] * xv[i].y;
            acc.z += ev[i] * xv[i].z;
            acc.w += ev[i] * xv[i].w;
            s += ev[i];
        }
    }
    for (; j < cnt; j += 2) {
        int idx = j + g;
        if (idx < cnt) {
            unsigned long long pk = __ldg(packs + idx);
            int src  = (int)(unsigned)(pk & 0xffffffffull);
            float ev = __uint_as_float((unsigned)(pk >> 32));
            float4 xv = __ldg(((const float4*)(g_xw + (size_t)src * 64)) + q);
            acc.x += ev * xv.x;
            acc.y += ev * xv.y;
            acc.z += ev * xv.z;
            acc.w += ev * xv.w;
            s += ev;
        }
    }
    // combine the two 16-lane groups
    acc.x += __shfl_xor_sync(0xffffffffu, acc.x, 16);
    acc.y += __shfl_xor_sync(0xffffffffu, acc.y, 16);
    acc.z += __shfl_xor_sync(0xffffffffu, acc.z, 16);
    acc.w += __shfl_xor_sync(0xffffffffu, acc.w, 16);
    s     += __shfl_xor_sync(0xffffffffu, s,     16);

    if (lane < 16) {
        float inv = 1.0f / (s + 1e-16f);
        float4 b = __ldg(((const float4*)bias) + q);
        float4 o = make_float4(acc.x * inv + b.x, acc.y * inv + b.y,
                               acc.z * inv + b.z, acc.w * inv + b.w);
        ((float4*)(out + (size_t)n * 64))[q] = o;
    }
}

// ---------------------------------------------------------------------------
extern "C" void kernel_launch(void* const* d_in, const int* in_sizes, int n_in,
                              void* d_out, int out_size) {
    const float* x    = nullptr;
    const int*   ei32 = nullptr;
    const float* ea   = nullptr;
    const float* W    = nullptr;
    const float* wa   = nullptr;
    const float* bias = nullptr;
    for (int i = 0; i < n_in; i++) {
        switch (in_sizes[i]) {
            case N_NODES * C:      x    = (const float*)d_in[i]; break;
            case 2 * N_EDGES:      ei32 = (const int*)d_in[i];   break;
            case N_EDGES * CE:     ea   = (const float*)d_in[i]; break;
            case C * C:            W    = (const float*)d_in[i]; break;
            case 2 * C + CE:       wa   = (const float*)d_in[i]; break;
            case C:                bias = (const float*)d_in[i]; break;
        }
    }
    float* out = (float*)d_out;

    k_detect<<<1, 256>>>(ei32);
    k_zero<<<(N_NODES + 255) / 256, 256>>>();
    k_gemm<<<(N_NODES + 127) / 128, 256>>>(x, W, wa);
    // 16 edges per warp -> 50000 warps -> 6250 blocks of 8 warps
    k_edgeC<<<(N_EDGES / 16 + 7) / 8, 256>>>(ei32, ea, wa);
    k_accum<<<(N_NODES + 7) / 8, 256>>>(bias, out);
}